// round 2
// baseline (speedup 1.0000x reference)
#include <cuda_runtime.h>
#include <math.h>

#define BB 64
#define TT 512
#define DIN 512
#define HH 1024

#define NCOLBLK 32   // blocks along hidden dim
#define NBGRP 4      // independent batch groups (separate barrier domains)
#define BROWS 16     // batch rows per block
#define BCOLS 32     // hidden cols per block
#define NTHR 256
#define ASTR 1028    // padded A-tile row stride (floats), 16B-aligned, bank-skewed

// Scratch: buf0 holds pre0 then h0 in place; buf1 holds pre1. h1 -> d_out.
__device__ float g_buf0[(size_t)BB * TT * HH];
__device__ float g_buf1[(size_t)BB * TT * HH];

// Per-batch-group grid barrier state (zero-initialized at module load; each
// barrier leaves count at 0, gen monotonically increases -> replay-safe).
__device__ unsigned int          g_bar_count[NBGRP];
__device__ volatile unsigned int g_bar_gen[NBGRP];

__device__ __forceinline__ void group_barrier(int bg)
{
    __syncthreads();
    __threadfence();                       // release h(t) writes to L2
    if (threadIdx.x == 0) {
        unsigned int gen = g_bar_gen[bg];
        unsigned int tkt = atomicAdd(&g_bar_count[bg], 1u);
        if (tkt == NCOLBLK - 1) {
            g_bar_count[bg] = 0;
            __threadfence();
            g_bar_gen[bg] = gen + 1;       // release
        } else {
            while (g_bar_gen[bg] == gen) { }   // volatile L2 spin
        }
    }
    __syncthreads();
}

// ---------------------------------------------------------------------------
// Big parallel GEMM: C[M,N] = A[M,K] @ W[N,K]^T + (b0[n] + b1[n])
// BM=64, BN=64, BK=16, 256 threads, 4x4 micro-tile.
// ---------------------------------------------------------------------------
__global__ __launch_bounds__(256) void pre_gemm_kernel(
    const float* __restrict__ A,
    const float* __restrict__ W,
    const float* __restrict__ b0,
    const float* __restrict__ b1,
    float* __restrict__ C,
    int K, int N)
{
    __shared__ float As[16][64];
    __shared__ float Ws[16][64];

    const int tid = threadIdx.x;
    const int tx = tid & 15;
    const int ty = tid >> 4;
    const int block_row = blockIdx.y * 64;
    const int block_col = blockIdx.x * 64;

    const int lrow = tid >> 2;
    const int lk   = (tid & 3) * 4;

    float acc[4][4] = {};

    for (int k0 = 0; k0 < K; k0 += 16) {
        float4 av = *(const float4*)&A[(size_t)(block_row + lrow) * K + k0 + lk];
        float4 wv = *(const float4*)&W[(size_t)(block_col + lrow) * K + k0 + lk];
        As[lk + 0][lrow] = av.x; As[lk + 1][lrow] = av.y;
        As[lk + 2][lrow] = av.z; As[lk + 3][lrow] = av.w;
        Ws[lk + 0][lrow] = wv.x; Ws[lk + 1][lrow] = wv.y;
        Ws[lk + 2][lrow] = wv.z; Ws[lk + 3][lrow] = wv.w;
        __syncthreads();

#pragma unroll
        for (int kk = 0; kk < 16; kk++) {
            float4 a4 = *(const float4*)&As[kk][ty * 4];
            float4 w4 = *(const float4*)&Ws[kk][tx * 4];
            float a[4] = {a4.x, a4.y, a4.z, a4.w};
            float w[4] = {w4.x, w4.y, w4.z, w4.w};
#pragma unroll
            for (int i = 0; i < 4; i++)
#pragma unroll
                for (int j = 0; j < 4; j++)
                    acc[i][j] += a[i] * w[j];
        }
        __syncthreads();
    }

    const int col = block_col + tx * 4;
    float bias[4];
#pragma unroll
    for (int j = 0; j < 4; j++) bias[j] = b0[col + j] + b1[col + j];

#pragma unroll
    for (int i = 0; i < 4; i++) {
        const int row = block_row + ty * 4 + i;
        float4 r;
        r.x = acc[i][0] + bias[0];
        r.y = acc[i][1] + bias[1];
        r.z = acc[i][2] + bias[2];
        r.w = acc[i][3] + bias[3];
        *(float4*)&C[(size_t)row * N + col] = r;
    }
}

// ---------------------------------------------------------------------------
// Persistent recurrent layer: for t in 0..T-1:
//   h(t) = tanh(pre[:,t,:] + h(t-1) @ Whh^T),  h written into hbase[:,t,:]
// One kernel runs all T steps. Each block owns a (16 batch x 32 col) tile,
// keeps its Whh slice (32x1024 f32, transposed) in SMEM for the whole kernel,
// and per step reloads only the h(t-1) tile (16x1024). Blocks in the same
// batch group synchronize via a 32-way L2 generation barrier each step.
// Grid: (32, 4) = 128 blocks, 1 per SM (197KB SMEM) -> single wave, safe spin.
// ---------------------------------------------------------------------------
__global__ __launch_bounds__(NTHR, 1) void rnn_layer_kernel(
    const float* __restrict__ pre,
    float* __restrict__ hbase,
    const float* __restrict__ Whh)
{
    extern __shared__ float sm[];
    float* Ws = sm;                     // [1024][32] : Ws[k*32 + c] (transposed)
    float* As = sm + HH * BCOLS;        // [16][ASTR]

    const int tid  = threadIdx.x;
    const int cb   = blockIdx.x;        // 0..31
    const int bg   = blockIdx.y;        // 0..3
    const int bcol = cb * BCOLS;
    const int brow = bg * BROWS;
    const size_t row_stride = (size_t)TT * HH;

    // Load this block's W slice once, transposed (one-time cost).
    for (int i = tid; i < BCOLS * HH / 4; i += NTHR) {
        int c  = i >> 8;                // 256 float4 per W row
        int kq = (i & 255) * 4;
        float4 w = *(const float4*)&Whh[(size_t)(bcol + c) * HH + kq];
        Ws[(kq + 0) * BCOLS + c] = w.x;
        Ws[(kq + 1) * BCOLS + c] = w.y;
        Ws[(kq + 2) * BCOLS + c] = w.z;
        Ws[(kq + 3) * BCOLS + c] = w.w;
    }
    __syncthreads();

    const int ty = tid >> 4;            // 0..15 : batch row
    const int tx = tid & 15;            // 0..15 : col pair (2 cols/thread)
    const float* wp = Ws + tx * 2;

    for (int t = 0; t < TT; t++) {
        float acc0 = 0.f, acc1 = 0.f;

        if (t > 0) {
            // stage h(t-1)[brow..brow+15][:] into SMEM (coalesced float4)
            const float* hsrc = hbase + (size_t)(t - 1) * HH;
            for (int i = tid; i < BROWS * HH / 4; i += NTHR) {
                int r  = i >> 8;
                int kq = (i & 255) * 4;
                float4 v = *(const float4*)&hsrc[(size_t)(brow + r) * row_stride + kq];
                *(float4*)&As[r * ASTR + kq] = v;
            }
            __syncthreads();

            const float* arow = As + ty * ASTR;
#pragma unroll 4
            for (int k = 0; k < HH; k += 4) {
                float4 a4 = *(const float4*)&arow[k];
                float2 w0 = *(const float2*)&wp[(k + 0) * BCOLS];
                float2 w1 = *(const float2*)&wp[(k + 1) * BCOLS];
                float2 w2 = *(const float2*)&wp[(k + 2) * BCOLS];
                float2 w3 = *(const float2*)&wp[(k + 3) * BCOLS];
                acc0 += a4.x * w0.x; acc1 += a4.x * w0.y;
                acc0 += a4.y * w1.x; acc1 += a4.y * w1.y;
                acc0 += a4.z * w2.x; acc1 += a4.z * w2.y;
                acc0 += a4.w * w3.x; acc1 += a4.w * w3.y;
            }
        }

        const size_t ob = (size_t)(brow + ty) * row_stride + (size_t)t * HH
                        + bcol + tx * 2;
        float2 p = *(const float2*)&pre[ob];
        float2 r;
        r.x = tanhf(p.x + acc0);
        r.y = tanhf(p.y + acc1);
        *(float2*)&hbase[ob] = r;

        group_barrier(bg);   // entry syncthreads also protects As reuse
    }
}

// ---------------------------------------------------------------------------
__global__ void finalize_kernel(float* __restrict__ out)
{
    int i = blockIdx.x * blockDim.x + threadIdx.x;   // over B*H
    if (i >= BB * HH) return;
    int b = i / HH;
    int h = i - b * HH;
    float* hfin = out + (size_t)BB * TT * HH;
    size_t src = (size_t)b * TT * HH + (size_t)(TT - 1) * HH + h;
    hfin[i] = g_buf0[src];
    hfin[(size_t)BB * HH + i] = out[src];
}

// ---------------------------------------------------------------------------

extern "C" void kernel_launch(void* const* d_in, const int* in_sizes, int n_in,
                              void* d_out, int out_size)
{
    const float* x      = (const float*)d_in[0];
    const float* W_ih0  = (const float*)d_in[1];
    const float* W_hh0  = (const float*)d_in[2];
    const float* b_ih0  = (const float*)d_in[3];
    const float* b_hh0  = (const float*)d_in[4];
    const float* W_ih1  = (const float*)d_in[5];
    const float* W_hh1  = (const float*)d_in[6];
    const float* b_ih1  = (const float*)d_in[7];
    const float* b_hh1  = (const float*)d_in[8];
    // d_in[9]=fc_w, d_in[10]=fc_b : computed-but-discarded in reference
    float* out = (float*)d_out;

    void* p0; cudaGetSymbolAddress(&p0, g_buf0);
    void* p1; cudaGetSymbolAddress(&p1, g_buf1);
    float* buf0 = (float*)p0;
    float* buf1 = (float*)p1;

    const int rnn_smem = (HH * BCOLS + BROWS * ASTR) * (int)sizeof(float); // 196864
    cudaFuncSetAttribute(rnn_layer_kernel,
                         cudaFuncAttributeMaxDynamicSharedMemorySize, rnn_smem);

    // 1) pre0 = X @ W_ih0^T + b_ih0 + b_hh0
    {
        dim3 grid(HH / 64, (BB * TT) / 64);
        pre_gemm_kernel<<<grid, 256>>>(x, W_ih0, b_ih0, b_hh0, buf0, DIN, HH);
    }

    // 2) layer-0 recurrence (persistent, in place over buf0)
    {
        dim3 grid(NCOLBLK, NBGRP);
        rnn_layer_kernel<<<grid, NTHR, rnn_smem>>>(buf0, buf0, W_hh0);
    }

    // 3) pre1 = H0 @ W_ih1^T + b_ih1 + b_hh1
    {
        dim3 grid(HH / 64, (BB * TT) / 64);
        pre_gemm_kernel<<<grid, 256>>>(buf0, W_ih1, b_ih1, b_hh1, buf1, HH, HH);
    }

    // 4) layer-1 recurrence (persistent, writes h1 into outputs region)
    {
        dim3 grid(NCOLBLK, NBGRP);
        rnn_layer_kernel<<<grid, NTHR, rnn_smem>>>(buf1, out, W_hh1);
    }

    // 5) h_final
    finalize_kernel<<<(BB * HH + 255) / 256, 256>>>(out);
}